// round 9
// baseline (speedup 1.0000x reference)
#include <cuda_runtime.h>

#define HDIM 2048
#define NT 512
#define MAXS 1000

typedef unsigned long long ull;

// ---------------- packed f32x2 helpers ----------------
__device__ __forceinline__ ull pk2(float lo, float hi) {
    ull r; asm("mov.b64 %0, {%1,%2};" : "=l"(r) : "f"(lo), "f"(hi)); return r;
}
__device__ __forceinline__ void upk2(ull v, float& lo, float& hi) {
    asm("mov.b64 {%0,%1}, %2;" : "=f"(lo), "=f"(hi) : "l"(v));
}
__device__ __forceinline__ ull fma2_(ull a, ull b, ull c) {
    ull d; asm("fma.rn.f32x2 %0, %1, %2, %3;" : "=l"(d) : "l"(a), "l"(b), "l"(c)); return d;
}
__device__ __forceinline__ float tanha(float x) {
    float y; asm("tanh.approx.f32 %0, %1;" : "=f"(y) : "f"(x)); return y;
}
// full-warp butterfly sum (5 shfl); independent calls pipeline
__device__ __forceinline__ float warp_sum(float v) {
    #pragma unroll
    for (int off = 16; off > 0; off >>= 1)
        v += __shfl_xor_sync(0xffffffffu, v, off);
    return v;
}

// ---------------- threefry2x32 (JAX), key = (0, 42) ----------------
__device__ __forceinline__ void threefry2x32(unsigned k1, unsigned k2,
                                             unsigned x0, unsigned x1,
                                             unsigned* o0, unsigned* o1) {
    unsigned ks0 = k1, ks1 = k2, ks2 = k1 ^ k2 ^ 0x1BD11BDAu;
    x0 += ks0; x1 += ks1;
#define TF_R(r) { x0 += x1; x1 = (x1 << (r)) | (x1 >> (32 - (r))); x1 ^= x0; }
    TF_R(13) TF_R(15) TF_R(26) TF_R(6)   x0 += ks1; x1 += ks2 + 1u;
    TF_R(17) TF_R(29) TF_R(16) TF_R(24)  x0 += ks2; x1 += ks0 + 2u;
    TF_R(13) TF_R(15) TF_R(26) TF_R(6)   x0 += ks0; x1 += ks1 + 3u;
    TF_R(17) TF_R(29) TF_R(16) TF_R(24)  x0 += ks1; x1 += ks2 + 4u;
    TF_R(13) TF_R(15) TF_R(26) TF_R(6)   x0 += ks2; x1 += ks0 + 5u;
#undef TF_R
    *o0 = x0; *o1 = x1;
}

// XLA ErfInv32 (Giles) polynomial — matches lax.erf_inv on f32.
__device__ __forceinline__ float erfinv_xla(float x) {
    float w = -logf((1.0f - x) * (1.0f + x));
    float p;
    if (w < 5.0f) {
        w -= 2.5f;
        p = 2.81022636e-08f;
        p = fmaf(p, w, 3.43273939e-07f);
        p = fmaf(p, w, -3.5233877e-06f);
        p = fmaf(p, w, -4.39150654e-06f);
        p = fmaf(p, w, 0.00021858087f);
        p = fmaf(p, w, -0.00125372503f);
        p = fmaf(p, w, -0.00417768164f);
        p = fmaf(p, w, 0.246640727f);
        p = fmaf(p, w, 1.50140941f);
    } else {
        w = sqrtf(w) - 3.0f;
        p = -0.000200214257f;
        p = fmaf(p, w, 0.000100950558f);
        p = fmaf(p, w, 0.00134934322f);
        p = fmaf(p, w, -0.00367342844f);
        p = fmaf(p, w, 0.00573950773f);
        p = fmaf(p, w, -0.0076224613f);
        p = fmaf(p, w, 0.00943887047f);
        p = fmaf(p, w, 1.00167406f);
        p = fmaf(p, w, 2.83297682f);
    }
    return p * x;
}

__device__ __forceinline__ float bits_to_normal(unsigned bits) {
    const float lo = -0.99999994f;            // nextafterf(-1, 0)
    const float span = 1.0f - lo;
    float f = __uint_as_float((bits >> 9) | 0x3f800000u) - 1.0f;  // [0,1)
    float u = fmaxf(lo, f * span + lo);
    return 1.41421356f * erfinv_xla(u);
}

__global__ void __launch_bounds__(NT, 1)
sketch_decoder_kernel(const float* __restrict__ W_ih,
                      const float* __restrict__ b_ih,
                      const float* __restrict__ b_hh,
                      const float* __restrict__ W_lin,
                      const float* __restrict__ b_lin,
                      const int*   __restrict__ msp,
                      float* __restrict__ out) {
    __shared__ float  s_part[16][8];     // per-warp partials (16 warps x 7, padded)
    __shared__ float  s_last[4];         // sx, sy, sm0, sm1  (sm2 folded via sum=1)
    __shared__ float  s_red[8];
    __shared__ int    s_done;
    __shared__ float2 s_eps[MAXS];

    const int tid = threadIdx.x;
    const int warp = tid >> 5, lane = tid & 31;
    int ms = msp[0];
    if (ms < 0) ms = 0;
    if (ms > MAXS) ms = MAXS;

    // ---- init output buffer: row0 = [0,0,1,0,0], rest = [0,0,0,0,1] ----
    for (int idx = tid; idx < ms * 5; idx += NT) {
        int r = idx / 5, c = idx - r * 5;
        out[idx] = (r == 0) ? ((c == 2) ? 1.0f : 0.0f)
                            : ((c == 4) ? 1.0f : 0.0f);
    }

    // ---- precompute eps (JAX partitionable threefry, key(42)) ----
    for (int i = tid; i < ms; i += NT) {
        unsigned r0, r1;
        threefry2x32(0u, 42u, 0u, (unsigned)(2 * i), &r0, &r1);
        float ex = bits_to_normal(r0 ^ r1);
        threefry2x32(0u, 42u, 0u, (unsigned)(2 * i + 1), &r0, &r1);
        float ey = bits_to_normal(r0 ^ r1);
        s_eps[i] = make_float2(ex, ey);
    }

    if (tid == 0) {
        s_last[0] = 0.0f; s_last[1] = 0.0f;   // sx, sy
        s_last[2] = 1.0f; s_last[3] = 0.0f;   // sm0, sm1 (init row [0,0,1,0,0])
        s_done = 0;
    }
    // per-thread bias for the reduce warps (lane 0 of warps 0-6 only)
    const float myblin = (warp < 7 && lane == 0) ? b_lin[warp] : 0.0f;

    // ---- register-resident packed weights (4 elements / thread = 2 pairs) ----
    // i,o gate rows pre-scaled by 0.5 (sigmoid via 0.5*tanh(0.5x)+0.5).
    // sum-1 fold: gate = w0*l0 + w1*l1 + (w2-w4)*sm0 + (w3-w4)*sm1 + (b + w4).
    ull wi[2][4], wg[2][4], wo[2][4], wl[2][7], bi[2], bg[2], bo[2];
    #pragma unroll
    for (int q = 0; q < 2; q++) {
        const int e0 = tid + (2 * q) * NT;
        const int e1 = e0 + NT;
        const int g0 = 2 * HDIM + e0, g1 = 2 * HDIM + e1;
        const int o0 = 3 * HDIM + e0, o1 = 3 * HDIM + e1;
        #pragma unroll
        for (int c = 0; c < 2; c++) {   // l0, l1 coefficients
            wi[q][c] = pk2(0.5f * W_ih[e0 * 5 + c], 0.5f * W_ih[e1 * 5 + c]);
            wg[q][c] = pk2(W_ih[g0 * 5 + c],        W_ih[g1 * 5 + c]);
            wo[q][c] = pk2(0.5f * W_ih[o0 * 5 + c], 0.5f * W_ih[o1 * 5 + c]);
        }
        #pragma unroll
        for (int c = 2; c < 4; c++) {   // folded sm0, sm1 coefficients
            wi[q][c] = pk2(0.5f * (W_ih[e0 * 5 + c] - W_ih[e0 * 5 + 4]),
                           0.5f * (W_ih[e1 * 5 + c] - W_ih[e1 * 5 + 4]));
            wg[q][c] = pk2(W_ih[g0 * 5 + c] - W_ih[g0 * 5 + 4],
                           W_ih[g1 * 5 + c] - W_ih[g1 * 5 + 4]);
            wo[q][c] = pk2(0.5f * (W_ih[o0 * 5 + c] - W_ih[o0 * 5 + 4]),
                           0.5f * (W_ih[o1 * 5 + c] - W_ih[o1 * 5 + 4]));
        }
        bi[q] = pk2(0.5f * (b_ih[e0] + b_hh[e0] + W_ih[e0 * 5 + 4]),
                    0.5f * (b_ih[e1] + b_hh[e1] + W_ih[e1 * 5 + 4]));
        bg[q] = pk2(b_ih[g0] + b_hh[g0] + W_ih[g0 * 5 + 4],
                    b_ih[g1] + b_hh[g1] + W_ih[g1 * 5 + 4]);
        bo[q] = pk2(0.5f * (b_ih[o0] + b_hh[o0] + W_ih[o0 * 5 + 4]),
                    0.5f * (b_ih[o1] + b_hh[o1] + W_ih[o1 * 5 + 4]));
        #pragma unroll
        for (int k = 0; k < 7; k++)
            wl[q][k] = pk2(W_lin[k * HDIM + e0], W_lin[k * HDIM + e1]);
    }

    const float L2E = 1.442695041f;

    __syncthreads();

    // step 0 of the reference is a provable no-op (write gated by i>0) -> start at 1
    for (int i = 1; i < ms; i++) {
        // prefetch eps for the tail (off the critical path)
        float2 ep = make_float2(0.f, 0.f);
        if (tid == 0) ep = s_eps[i];

        ull lp[4];
        #pragma unroll
        for (int c = 0; c < 4; c++) { float v = s_last[c]; lp[c] = pk2(v, v); }

        ull acc[7];
        #pragma unroll
        for (int k = 0; k < 7; k++) acc[k] = 0ull;

        #pragma unroll
        for (int q = 0; q < 2; q++) {
            ull gi = bi[q], gg = bg[q], go = bo[q];
            #pragma unroll
            for (int c = 0; c < 4; c++) {
                gi = fma2_(wi[q][c], lp[c], gi);
                gg = fma2_(wg[q][c], lp[c], gg);
                go = fma2_(wo[q][c], lp[c], go);
            }
            float i0, i1, g0, g1, o0, o1;
            upk2(gi, i0, i1); upk2(gg, g0, g1); upk2(go, o0, o1);
            // sigmoid(x) = 0.5*tanh(0.5x)+0.5 ; 0.5 pre-folded into gi/go
            float si0 = fmaf(tanha(i0), 0.5f, 0.5f);
            float si1 = fmaf(tanha(i1), 0.5f, 0.5f);
            float so0 = fmaf(tanha(o0), 0.5f, 0.5f);
            float so1 = fmaf(tanha(o1), 0.5f, 0.5f);
            float c0 = si0 * tanha(g0);
            float c1 = si1 * tanha(g1);
            // Taylor-9 tanh (|c| small; validated in R4 at rel_err 2.9e-7)
            float t0 = c0 * c0, t1 = c1 * c1;
            float p0 = fmaf(0.02186949f, t0, -0.05396825f);
            float p1 = fmaf(0.02186949f, t1, -0.05396825f);
            p0 = fmaf(p0, t0, 0.13333334f);
            p1 = fmaf(p1, t1, 0.13333334f);
            p0 = fmaf(p0, t0, -0.33333334f);
            p1 = fmaf(p1, t1, -0.33333334f);
            p0 = fmaf(p0, t0, 1.0f);
            p1 = fmaf(p1, t1, 1.0f);
            float h0 = so0 * (p0 * c0);
            float h1 = so1 * (p1 * c1);
            ull hp = pk2(h0, h1);
            #pragma unroll
            for (int k = 0; k < 7; k++)
                acc[k] = fma2_(wl[q][k], hp, acc[k]);
        }

        // intra-warp reduction: 7 independent butterfly chains (pipelined)
        float s[7];
        #pragma unroll
        for (int k = 0; k < 7; k++) {
            float a0, a1; upk2(acc[k], a0, a1);
            s[k] = warp_sum(a0 + a1);
        }
        if (lane == 0) {
            #pragma unroll
            for (int k = 0; k < 7; k++) s_part[warp][k] = s[k];
        }
        __syncthreads();

        // warps 0-6: cross-warp reduce (16 partials) + per-output nonlinearity:
        //   k=0,2 : tanh(o_k)            (raw, for sx/sy)
        //   k=1,3 : exp(0.5*tanh(o_k))   (sig_x / sig_y)
        //   k=4..6: exp(tanh(o_k))       (unnormalized softmax; arg in [-1,1])
        if (warp < 7) {
            float v = (lane < 16) ? s_part[lane][warp] : 0.0f;
            #pragma unroll
            for (int off = 8; off > 0; off >>= 1)
                v += __shfl_xor_sync(0xffffffffu, v, off);
            // lanes 0..15 all hold the 16-warp sum now (lane 0 used below)
            if (lane == 0) {
                float o = tanha(v + myblin);
                float r;
                if (warp == 1 || warp == 3)
                    r = exp2f(0.5f * L2E * o);
                else if (warp >= 4)
                    r = exp2f(L2E * o);
                else
                    r = o;
                s_red[warp] = r;
            }
            // named barrier among warps 0-6 only (224 threads)
            asm volatile("bar.sync 9, 224;" ::: "memory");
        }

        // lean scalar tail (warp 0 passed the named barrier -> s_red complete)
        if (tid == 0) {
            float o0 = s_red[0], sigx = s_red[1], o2 = s_red[2], sigy = s_red[3];
            float e4 = s_red[4], e5 = s_red[5], e6 = s_red[6];
            float inv = __frcp_rn(e4 + e5 + e6);
            float sm0 = e4 * inv, sm1 = e5 * inv, sm2 = e6 * inv;
            float sx = fmaf(sigx, ep.x, o0);
            float sy = fmaf(sigy, ep.y, o2);
            s_last[0] = sx; s_last[1] = sy;
            s_last[2] = sm0; s_last[3] = sm1;
            // argmax(row[2:]) == 2  <=>  sm2 strictly beats both (first-max-wins)
            if (sm2 > sm0 && sm2 > sm1) s_done = 1;
            float* row = out + i * 5;   // n == i until termination
            row[0] = sx; row[1] = sy; row[2] = sm0; row[3] = sm1; row[4] = sm2;
        }
        __syncthreads();
        if (s_done) break;   // remaining steps are provable no-ops
    }
}

extern "C" void kernel_launch(void* const* d_in, const int* in_sizes, int n_in,
                              void* d_out, int out_size) {
    const float* W_ih  = (const float*)d_in[0];
    // d_in[1] = W_hh: multiplied by a provably-zero hidden state -> unused.
    const float* b_ih  = (const float*)d_in[2];
    const float* b_hh  = (const float*)d_in[3];
    const float* W_lin = (const float*)d_in[4];
    const float* b_lin = (const float*)d_in[5];
    const int*   msp   = (const int*)d_in[6];
    float* out = (float*)d_out;

    sketch_decoder_kernel<<<1, NT>>>(W_ih, b_ih, b_hh, W_lin, b_lin, msp, out);
    (void)in_sizes; (void)n_in; (void)out_size;
}

// round 10
// speedup vs baseline: 1.4140x; 1.4140x over previous
#include <cuda_runtime.h>

#define HDIM 2048
#define NT 256
#define MAXS 1000

typedef unsigned long long ull;

// ---------------- packed f32x2 helpers ----------------
__device__ __forceinline__ ull pk2(float lo, float hi) {
    ull r; asm("mov.b64 %0, {%1,%2};" : "=l"(r) : "f"(lo), "f"(hi)); return r;
}
__device__ __forceinline__ void upk2(ull v, float& lo, float& hi) {
    asm("mov.b64 {%0,%1}, %2;" : "=f"(lo), "=f"(hi) : "l"(v));
}
__device__ __forceinline__ ull fma2_(ull a, ull b, ull c) {
    ull d; asm("fma.rn.f32x2 %0, %1, %2, %3;" : "=l"(d) : "l"(a), "l"(b), "l"(c)); return d;
}
__device__ __forceinline__ float tanha(float x) {
    float y; asm("tanh.approx.f32 %0, %1;" : "=f"(y) : "f"(x)); return y;
}

// ---------------- threefry2x32 (JAX), key = (0, 42) ----------------
__device__ __forceinline__ void threefry2x32(unsigned k1, unsigned k2,
                                             unsigned x0, unsigned x1,
                                             unsigned* o0, unsigned* o1) {
    unsigned ks0 = k1, ks1 = k2, ks2 = k1 ^ k2 ^ 0x1BD11BDAu;
    x0 += ks0; x1 += ks1;
#define TF_R(r) { x0 += x1; x1 = (x1 << (r)) | (x1 >> (32 - (r))); x1 ^= x0; }
    TF_R(13) TF_R(15) TF_R(26) TF_R(6)   x0 += ks1; x1 += ks2 + 1u;
    TF_R(17) TF_R(29) TF_R(16) TF_R(24)  x0 += ks2; x1 += ks0 + 2u;
    TF_R(13) TF_R(15) TF_R(26) TF_R(6)   x0 += ks0; x1 += ks1 + 3u;
    TF_R(17) TF_R(29) TF_R(16) TF_R(24)  x0 += ks1; x1 += ks2 + 4u;
    TF_R(13) TF_R(15) TF_R(26) TF_R(6)   x0 += ks2; x1 += ks0 + 5u;
#undef TF_R
    *o0 = x0; *o1 = x1;
}

// XLA ErfInv32 (Giles) polynomial — matches lax.erf_inv on f32.
__device__ __forceinline__ float erfinv_xla(float x) {
    float w = -logf((1.0f - x) * (1.0f + x));
    float p;
    if (w < 5.0f) {
        w -= 2.5f;
        p = 2.81022636e-08f;
        p = fmaf(p, w, 3.43273939e-07f);
        p = fmaf(p, w, -3.5233877e-06f);
        p = fmaf(p, w, -4.39150654e-06f);
        p = fmaf(p, w, 0.00021858087f);
        p = fmaf(p, w, -0.00125372503f);
        p = fmaf(p, w, -0.00417768164f);
        p = fmaf(p, w, 0.246640727f);
        p = fmaf(p, w, 1.50140941f);
    } else {
        w = sqrtf(w) - 3.0f;
        p = -0.000200214257f;
        p = fmaf(p, w, 0.000100950558f);
        p = fmaf(p, w, 0.00134934322f);
        p = fmaf(p, w, -0.00367342844f);
        p = fmaf(p, w, 0.00573950773f);
        p = fmaf(p, w, -0.0076224613f);
        p = fmaf(p, w, 0.00943887047f);
        p = fmaf(p, w, 1.00167406f);
        p = fmaf(p, w, 2.83297682f);
    }
    return p * x;
}

__device__ __forceinline__ float bits_to_normal(unsigned bits) {
    const float lo = -0.99999994f;            // nextafterf(-1, 0)
    const float span = 1.0f - lo;
    float f = __uint_as_float((bits >> 9) | 0x3f800000u) - 1.0f;  // [0,1)
    float u = fmaxf(lo, f * span + lo);
    return 1.41421356f * erfinv_xla(u);
}

__global__ void __launch_bounds__(NT, 1)
sketch_decoder_kernel(const float* __restrict__ W_ih,
                      const float* __restrict__ b_ih,
                      const float* __restrict__ b_hh,
                      const float* __restrict__ W_lin,
                      const float* __restrict__ b_lin,
                      const int*   __restrict__ msp,
                      float* __restrict__ out) {
    __shared__ float  s_acc[7][NT];      // partial sums, row-contiguous (float4 reduce)
    __shared__ float4 s_lastv;           // {sx, sy, sm0, sm1}; sm2 = 1-sm0-sm1 folded
    __shared__ float  s_red[8];
    __shared__ int    s_done;
    __shared__ float2 s_eps[MAXS];

    const int tid = threadIdx.x;
    const int warp = tid >> 5, lane = tid & 31;
    int ms = msp[0];
    if (ms < 0) ms = 0;
    if (ms > MAXS) ms = MAXS;

    // ---- init output buffer: row0 = [0,0,1,0,0], rest = [0,0,0,0,1] ----
    for (int idx = tid; idx < ms * 5; idx += NT) {
        int r = idx / 5, c = idx - r * 5;
        out[idx] = (r == 0) ? ((c == 2) ? 1.0f : 0.0f)
                            : ((c == 4) ? 1.0f : 0.0f);
    }

    // ---- precompute eps (JAX partitionable threefry, key(42)) ----
    for (int i = tid; i < ms; i += NT) {
        unsigned r0, r1;
        threefry2x32(0u, 42u, 0u, (unsigned)(2 * i), &r0, &r1);
        float ex = bits_to_normal(r0 ^ r1);
        threefry2x32(0u, 42u, 0u, (unsigned)(2 * i + 1), &r0, &r1);
        float ey = bits_to_normal(r0 ^ r1);
        s_eps[i] = make_float2(ex, ey);
    }

    if (tid == 0) {
        s_lastv = make_float4(0.0f, 0.0f, 1.0f, 0.0f);  // init row [0,0,1,0,0]
        s_done = 0;
    }
    // per-thread bias for the reduce warps (lane 0 of warps 0-6 only)
    const float myblin = (warp < 7 && lane == 0) ? b_lin[warp] : 0.0f;

    // ---- register-resident packed weights (8 elements / thread = 4 pairs) ----
    // i,o gate rows pre-scaled by 0.5 (sigmoid via 0.5*tanh(0.5x)+0.5).
    // sum-1 fold: gate = w0*l0 + w1*l1 + (w2-w4)*sm0 + (w3-w4)*sm1 + (b + w4).
    ull wi[4][4], wg[4][4], wo[4][4], wl[4][7], bi[4], bg[4], bo[4];
    #pragma unroll
    for (int q = 0; q < 4; q++) {
        const int e0 = tid + (2 * q) * NT;
        const int e1 = e0 + NT;
        const int g0 = 2 * HDIM + e0, g1 = 2 * HDIM + e1;
        const int o0 = 3 * HDIM + e0, o1 = 3 * HDIM + e1;
        #pragma unroll
        for (int c = 0; c < 2; c++) {   // l0, l1 coefficients
            wi[q][c] = pk2(0.5f * W_ih[e0 * 5 + c], 0.5f * W_ih[e1 * 5 + c]);
            wg[q][c] = pk2(W_ih[g0 * 5 + c],        W_ih[g1 * 5 + c]);
            wo[q][c] = pk2(0.5f * W_ih[o0 * 5 + c], 0.5f * W_ih[o1 * 5 + c]);
        }
        #pragma unroll
        for (int c = 2; c < 4; c++) {   // folded sm0, sm1 coefficients
            wi[q][c] = pk2(0.5f * (W_ih[e0 * 5 + c] - W_ih[e0 * 5 + 4]),
                           0.5f * (W_ih[e1 * 5 + c] - W_ih[e1 * 5 + 4]));
            wg[q][c] = pk2(W_ih[g0 * 5 + c] - W_ih[g0 * 5 + 4],
                           W_ih[g1 * 5 + c] - W_ih[g1 * 5 + 4]);
            wo[q][c] = pk2(0.5f * (W_ih[o0 * 5 + c] - W_ih[o0 * 5 + 4]),
                           0.5f * (W_ih[o1 * 5 + c] - W_ih[o1 * 5 + 4]));
        }
        bi[q] = pk2(0.5f * (b_ih[e0] + b_hh[e0] + W_ih[e0 * 5 + 4]),
                    0.5f * (b_ih[e1] + b_hh[e1] + W_ih[e1 * 5 + 4]));
        bg[q] = pk2(b_ih[g0] + b_hh[g0] + W_ih[g0 * 5 + 4],
                    b_ih[g1] + b_hh[g1] + W_ih[g1 * 5 + 4]);
        bo[q] = pk2(0.5f * (b_ih[o0] + b_hh[o0] + W_ih[o0 * 5 + 4]),
                    0.5f * (b_ih[o1] + b_hh[o1] + W_ih[o1 * 5 + 4]));
        #pragma unroll
        for (int k = 0; k < 7; k++)
            wl[q][k] = pk2(W_lin[k * HDIM + e0], W_lin[k * HDIM + e1]);
    }

    const float L2E = 1.442695041f;

    __syncthreads();

    // step 0 of the reference is a provable no-op (write gated by i>0) -> start at 1
    for (int i = 1; i < ms; i++) {
        // prefetch eps for the tail (off the critical path)
        float2 ep = make_float2(0.f, 0.f);
        if (tid == 0) ep = s_eps[i];

        const float4 lv = s_lastv;     // single broadcast LDS.128
        ull lp[4];
        lp[0] = pk2(lv.x, lv.x); lp[1] = pk2(lv.y, lv.y);
        lp[2] = pk2(lv.z, lv.z); lp[3] = pk2(lv.w, lv.w);

        ull acc[7];
        #pragma unroll
        for (int k = 0; k < 7; k++) acc[k] = 0ull;

        #pragma unroll
        for (int q = 0; q < 4; q++) {
            ull gi = bi[q], gg = bg[q], go = bo[q];
            #pragma unroll
            for (int c = 0; c < 4; c++) {
                gi = fma2_(wi[q][c], lp[c], gi);
                gg = fma2_(wg[q][c], lp[c], gg);
                go = fma2_(wo[q][c], lp[c], go);
            }
            float i0, i1, g0, g1, o0, o1;
            upk2(gi, i0, i1); upk2(gg, g0, g1); upk2(go, o0, o1);
            // sigmoid(x) = 0.5*tanh(0.5x)+0.5 ; 0.5 pre-folded into gi/go
            float si0 = fmaf(tanha(i0), 0.5f, 0.5f);
            float si1 = fmaf(tanha(i1), 0.5f, 0.5f);
            float so0 = fmaf(tanha(o0), 0.5f, 0.5f);
            float so1 = fmaf(tanha(o1), 0.5f, 0.5f);
            float c0 = si0 * tanha(g0);
            float c1 = si1 * tanha(g1);
            float tc0, tc1;
            if (q < 2) {
                // Taylor-9 tanh on FMA pipe (|c| small; validated R4/R8 at ~3e-7)
                float t0 = c0 * c0, t1 = c1 * c1;
                float p0 = fmaf(0.02186949f, t0, -0.05396825f);
                float p1 = fmaf(0.02186949f, t1, -0.05396825f);
                p0 = fmaf(p0, t0, 0.13333334f);
                p1 = fmaf(p1, t1, 0.13333334f);
                p0 = fmaf(p0, t0, -0.33333334f);
                p1 = fmaf(p1, t1, -0.33333334f);
                p0 = fmaf(p0, t0, 1.0f);
                p1 = fmaf(p1, t1, 1.0f);
                tc0 = p0 * c0; tc1 = p1 * c1;
            } else {
                // MUFU path (pipe balancing: both pipes ~equal busy)
                tc0 = tanha(c0); tc1 = tanha(c1);
            }
            float h0 = so0 * tc0;
            float h1 = so1 * tc1;
            ull hp = pk2(h0, h1);
            #pragma unroll
            for (int k = 0; k < 7; k++)
                acc[k] = fma2_(wl[q][k], hp, acc[k]);
        }

        #pragma unroll
        for (int k = 0; k < 7; k++) {
            float a0, a1; upk2(acc[k], a0, a1);
            s_acc[k][tid] = a0 + a1;
        }
        __syncthreads();

        // warps 0-6: reduce output k=warp over 256 partials, then nonlinearity:
        //   k=0,2 : tanh(o_k)            (raw, for sx/sy)
        //   k=1,3 : exp(0.5*tanh(o_k))   (sig_x / sig_y)
        //   k=4..6: exp(tanh(o_k))       (unnormalized softmax; arg in [-1,1])
        if (warp < 7) {
            const float4* row = (const float4*)s_acc[warp];
            float4 v0 = row[lane];
            float4 v1 = row[lane + 32];
            float v = ((v0.x + v0.y) + (v0.z + v0.w))
                    + ((v1.x + v1.y) + (v1.z + v1.w));
            // 3 xor rounds -> lane0 holds sum over lanes == 0 (mod 4)
            v += __shfl_xor_sync(0xffffffffu, v, 16);
            v += __shfl_xor_sync(0xffffffffu, v, 8);
            v += __shfl_xor_sync(0xffffffffu, v, 4);
            // parallel gather of the 3 remaining mod-4 classes
            float g1 = __shfl_sync(0xffffffffu, v, 1);
            float g2 = __shfl_sync(0xffffffffu, v, 2);
            float g3 = __shfl_sync(0xffffffffu, v, 3);
            if (lane == 0) {
                float s = (v + g1) + (g2 + g3);
                float o = tanha(s + myblin);
                float r;
                if (warp == 1 || warp == 3)
                    r = exp2f(0.5f * L2E * o);
                else if (warp >= 4)
                    r = exp2f(L2E * o);
                else
                    r = o;
                s_red[warp] = r;
            }
            // named barrier among warps 0-6 only (224 threads)
            asm volatile("bar.sync 9, 224;" ::: "memory");
        }

        // lean scalar tail (warp 0 passed the named barrier -> s_red complete)
        if (tid == 0) {
            float o0 = s_red[0], sigx = s_red[1], o2 = s_red[2], sigy = s_red[3];
            float e4 = s_red[4], e5 = s_red[5], e6 = s_red[6];
            float inv = __frcp_rn(e4 + e5 + e6);
            float sm0 = e4 * inv, sm1 = e5 * inv;
            float sx = fmaf(sigx, ep.x, o0);
            float sy = fmaf(sigy, ep.y, o2);
            s_lastv = make_float4(sx, sy, sm0, sm1);
            // argmax(row[2:]) == 2  <=>  e6 strictly beats both (inv > 0 preserved)
            if (e6 > e4 && e6 > e5) s_done = 1;
            float* row = out + i * 5;   // n == i until termination
            float sm2 = e6 * inv;
            row[0] = sx; row[1] = sy; row[2] = sm0; row[3] = sm1; row[4] = sm2;
        }
        __syncthreads();
        if (s_done) break;   // remaining steps are provable no-ops
    }
}

extern "C" void kernel_launch(void* const* d_in, const int* in_sizes, int n_in,
                              void* d_out, int out_size) {
    const float* W_ih  = (const float*)d_in[0];
    // d_in[1] = W_hh: multiplied by a provably-zero hidden state -> unused.
    const float* b_ih  = (const float*)d_in[2];
    const float* b_hh  = (const float*)d_in[3];
    const float* W_lin = (const float*)d_in[4];
    const float* b_lin = (const float*)d_in[5];
    const int*   msp   = (const int*)d_in[6];
    float* out = (float*)d_out;

    sketch_decoder_kernel<<<1, NT>>>(W_ih, b_ih, b_hh, W_lin, b_lin, msp, out);
    (void)in_sizes; (void)n_in; (void)out_size;
}

// round 12
// speedup vs baseline: 1.4438x; 1.0211x over previous
#include <cuda_runtime.h>

#define HDIM 2048
#define NT 256
#define MAXS 1000

typedef unsigned long long ull;

// ---------------- packed f32x2 helpers ----------------
__device__ __forceinline__ ull pk2(float lo, float hi) {
    ull r; asm("mov.b64 %0, {%1,%2};" : "=l"(r) : "f"(lo), "f"(hi)); return r;
}
__device__ __forceinline__ void upk2(ull v, float& lo, float& hi) {
    asm("mov.b64 {%0,%1}, %2;" : "=f"(lo), "=f"(hi) : "l"(v));
}
__device__ __forceinline__ ull fma2_(ull a, ull b, ull c) {
    ull d; asm("fma.rn.f32x2 %0, %1, %2, %3;" : "=l"(d) : "l"(a), "l"(b), "l"(c)); return d;
}
__device__ __forceinline__ float tanha(float x) {
    float y; asm("tanh.approx.f32 %0, %1;" : "=f"(y) : "f"(x)); return y;
}

// ---------------- threefry2x32 (JAX), key = (0, 42) ----------------
__device__ __forceinline__ void threefry2x32(unsigned k1, unsigned k2,
                                             unsigned x0, unsigned x1,
                                             unsigned* o0, unsigned* o1) {
    unsigned ks0 = k1, ks1 = k2, ks2 = k1 ^ k2 ^ 0x1BD11BDAu;
    x0 += ks0; x1 += ks1;
#define TF_R(r) { x0 += x1; x1 = (x1 << (r)) | (x1 >> (32 - (r))); x1 ^= x0; }
    TF_R(13) TF_R(15) TF_R(26) TF_R(6)   x0 += ks1; x1 += ks2 + 1u;
    TF_R(17) TF_R(29) TF_R(16) TF_R(24)  x0 += ks2; x1 += ks0 + 2u;
    TF_R(13) TF_R(15) TF_R(26) TF_R(6)   x0 += ks0; x1 += ks1 + 3u;
    TF_R(17) TF_R(29) TF_R(16) TF_R(24)  x0 += ks1; x1 += ks2 + 4u;
    TF_R(13) TF_R(15) TF_R(26) TF_R(6)   x0 += ks2; x1 += ks0 + 5u;
#undef TF_R
    *o0 = x0; *o1 = x1;
}

// XLA ErfInv32 (Giles) polynomial — matches lax.erf_inv on f32.
__device__ __forceinline__ float erfinv_xla(float x) {
    float w = -logf((1.0f - x) * (1.0f + x));
    float p;
    if (w < 5.0f) {
        w -= 2.5f;
        p = 2.81022636e-08f;
        p = fmaf(p, w, 3.43273939e-07f);
        p = fmaf(p, w, -3.5233877e-06f);
        p = fmaf(p, w, -4.39150654e-06f);
        p = fmaf(p, w, 0.00021858087f);
        p = fmaf(p, w, -0.00125372503f);
        p = fmaf(p, w, -0.00417768164f);
        p = fmaf(p, w, 0.246640727f);
        p = fmaf(p, w, 1.50140941f);
    } else {
        w = sqrtf(w) - 3.0f;
        p = -0.000200214257f;
        p = fmaf(p, w, 0.000100950558f);
        p = fmaf(p, w, 0.00134934322f);
        p = fmaf(p, w, -0.00367342844f);
        p = fmaf(p, w, 0.00573950773f);
        p = fmaf(p, w, -0.0076224613f);
        p = fmaf(p, w, 0.00943887047f);
        p = fmaf(p, w, 1.00167406f);
        p = fmaf(p, w, 2.83297682f);
    }
    return p * x;
}

__device__ __forceinline__ float bits_to_normal(unsigned bits) {
    const float lo = -0.99999994f;            // nextafterf(-1, 0)
    const float span = 1.0f - lo;
    float f = __uint_as_float((bits >> 9) | 0x3f800000u) - 1.0f;  // [0,1)
    float u = fmaxf(lo, f * span + lo);
    return 1.41421356f * erfinv_xla(u);
}

__global__ void __launch_bounds__(NT, 1)
sketch_decoder_kernel(const float* __restrict__ W_ih,
                      const float* __restrict__ b_ih,
                      const float* __restrict__ b_hh,
                      const float* __restrict__ W_lin,
                      const float* __restrict__ b_lin,
                      const int*   __restrict__ msp,
                      float* __restrict__ out) {
    __shared__ float  s_acc[7][NT];      // partial sums, row-contiguous (float4 reduce)
    __shared__ float  s_red[8];          // 7 nonlinearized outputs (+pad), float4-aligned
    __shared__ float2 s_eps[MAXS];

    const int tid = threadIdx.x;
    const int warp = tid >> 5, lane = tid & 31;
    int ms = msp[0];
    if (ms < 0) ms = 0;
    if (ms > MAXS) ms = MAXS;

    // ---- init output buffer: row0 = [0,0,1,0,0], rest = [0,0,0,0,1] ----
    for (int idx = tid; idx < ms * 5; idx += NT) {
        int r = idx / 5, c = idx - r * 5;
        out[idx] = (r == 0) ? ((c == 2) ? 1.0f : 0.0f)
                            : ((c == 4) ? 1.0f : 0.0f);
    }

    // ---- precompute eps (JAX partitionable threefry, key(42)) ----
    for (int i = tid; i < ms; i += NT) {
        unsigned r0, r1;
        threefry2x32(0u, 42u, 0u, (unsigned)(2 * i), &r0, &r1);
        float ex = bits_to_normal(r0 ^ r1);
        threefry2x32(0u, 42u, 0u, (unsigned)(2 * i + 1), &r0, &r1);
        float ey = bits_to_normal(r0 ^ r1);
        s_eps[i] = make_float2(ex, ey);
    }
    if (tid == 0) s_red[7] = 0.0f;

    // per-thread bias for the reduce warps (lane 0 of warps 0-6 only)
    const float myblin = (warp < 7 && lane == 0) ? b_lin[warp] : 0.0f;

    // ---- register-resident packed weights (8 elements / thread = 4 pairs) ----
    // i,o gate rows pre-scaled by 0.5 (sigmoid via 0.5*tanh(0.5x)+0.5).
    // sum-1 fold: gate = w0*l0 + w1*l1 + (w2-w4)*sm0 + (w3-w4)*sm1 + (b + w4).
    ull wi[4][4], wg[4][4], wo[4][4], wl[4][7], bi[4], bg[4], bo[4];
    #pragma unroll
    for (int q = 0; q < 4; q++) {
        const int e0 = tid + (2 * q) * NT;
        const int e1 = e0 + NT;
        const int g0 = 2 * HDIM + e0, g1 = 2 * HDIM + e1;
        const int o0 = 3 * HDIM + e0, o1 = 3 * HDIM + e1;
        #pragma unroll
        for (int c = 0; c < 2; c++) {   // l0, l1 coefficients
            wi[q][c] = pk2(0.5f * W_ih[e0 * 5 + c], 0.5f * W_ih[e1 * 5 + c]);
            wg[q][c] = pk2(W_ih[g0 * 5 + c],        W_ih[g1 * 5 + c]);
            wo[q][c] = pk2(0.5f * W_ih[o0 * 5 + c], 0.5f * W_ih[o1 * 5 + c]);
        }
        #pragma unroll
        for (int c = 2; c < 4; c++) {   // folded sm0, sm1 coefficients
            wi[q][c] = pk2(0.5f * (W_ih[e0 * 5 + c] - W_ih[e0 * 5 + 4]),
                           0.5f * (W_ih[e1 * 5 + c] - W_ih[e1 * 5 + 4]));
            wg[q][c] = pk2(W_ih[g0 * 5 + c] - W_ih[g0 * 5 + 4],
                           W_ih[g1 * 5 + c] - W_ih[g1 * 5 + 4]);
            wo[q][c] = pk2(0.5f * (W_ih[o0 * 5 + c] - W_ih[o0 * 5 + 4]),
                           0.5f * (W_ih[o1 * 5 + c] - W_ih[o1 * 5 + 4]));
        }
        bi[q] = pk2(0.5f * (b_ih[e0] + b_hh[e0] + W_ih[e0 * 5 + 4]),
                    0.5f * (b_ih[e1] + b_hh[e1] + W_ih[e1 * 5 + 4]));
        bg[q] = pk2(b_ih[g0] + b_hh[g0] + W_ih[g0 * 5 + 4],
                    b_ih[g1] + b_hh[g1] + W_ih[g1 * 5 + 4]);
        bo[q] = pk2(0.5f * (b_ih[o0] + b_hh[o0] + W_ih[o0 * 5 + 4]),
                    0.5f * (b_ih[o1] + b_hh[o1] + W_ih[o1 * 5 + 4]));
        #pragma unroll
        for (int k = 0; k < 7; k++)
            wl[q][k] = pk2(W_lin[k * HDIM + e0], W_lin[k * HDIM + e1]);
    }

    const float L2E = 1.442695041f;

    // `last` lives in registers (redundant per-thread copy; identical IEEE
    // ops from identical s_red values -> identical across threads).
    float lx = 0.0f, ly = 0.0f, lm0 = 1.0f, lm1 = 0.0f;  // init row [0,0,1,0,0]

    __syncthreads();

    // step 0 of the reference is a provable no-op (write gated by i>0) -> start at 1
    for (int i = 1; i < ms; i++) {
        ull lp[4];
        lp[0] = pk2(lx, lx); lp[1] = pk2(ly, ly);
        lp[2] = pk2(lm0, lm0); lp[3] = pk2(lm1, lm1);

        ull acc[7];
        #pragma unroll
        for (int k = 0; k < 7; k++) acc[k] = 0ull;

        #pragma unroll
        for (int q = 0; q < 4; q++) {
            ull gi = bi[q], gg = bg[q], go = bo[q];
            #pragma unroll
            for (int c = 0; c < 4; c++) {
                gi = fma2_(wi[q][c], lp[c], gi);
                gg = fma2_(wg[q][c], lp[c], gg);
                go = fma2_(wo[q][c], lp[c], go);
            }
            float i0, i1, g0, g1, o0, o1;
            upk2(gi, i0, i1); upk2(gg, g0, g1); upk2(go, o0, o1);
            // sigmoid(x) = 0.5*tanh(0.5x)+0.5 ; 0.5 pre-folded into gi/go
            float si0 = fmaf(tanha(i0), 0.5f, 0.5f);
            float si1 = fmaf(tanha(i1), 0.5f, 0.5f);
            float so0 = fmaf(tanha(o0), 0.5f, 0.5f);
            float so1 = fmaf(tanha(o1), 0.5f, 0.5f);
            float c0 = si0 * tanha(g0);
            float c1 = si1 * tanha(g1);
            float tc0, tc1;
            if (q < 2) {
                // Taylor-9 tanh on FMA pipe (|c| small; validated R4/R8 at ~3e-7)
                float t0 = c0 * c0, t1 = c1 * c1;
                float p0 = fmaf(0.02186949f, t0, -0.05396825f);
                float p1 = fmaf(0.02186949f, t1, -0.05396825f);
                p0 = fmaf(p0, t0, 0.13333334f);
                p1 = fmaf(p1, t1, 0.13333334f);
                p0 = fmaf(p0, t0, -0.33333334f);
                p1 = fmaf(p1, t1, -0.33333334f);
                p0 = fmaf(p0, t0, 1.0f);
                p1 = fmaf(p1, t1, 1.0f);
                tc0 = p0 * c0; tc1 = p1 * c1;
            } else {
                // MUFU path (pipe balancing: both pipes ~equal busy)
                tc0 = tanha(c0); tc1 = tanha(c1);
            }
            float h0 = so0 * tc0;
            float h1 = so1 * tc1;
            ull hp = pk2(h0, h1);
            #pragma unroll
            for (int k = 0; k < 7; k++)
                acc[k] = fma2_(wl[q][k], hp, acc[k]);
        }

        #pragma unroll
        for (int k = 0; k < 7; k++) {
            float a0, a1; upk2(acc[k], a0, a1);
            s_acc[k][tid] = a0 + a1;
        }
        __syncthreads();   // bar1: s_acc complete

        // warps 0-6: reduce output k=warp over 256 partials, then nonlinearity:
        //   k=0,2 : tanh(o_k)            (raw, for sx/sy)
        //   k=1,3 : exp(0.5*tanh(o_k))   (sig_x / sig_y)
        //   k=4..6: exp(tanh(o_k))       (unnormalized softmax; arg in [-1,1])
        if (warp < 7) {
            const float4* row = (const float4*)s_acc[warp];
            float4 v0 = row[lane];
            float4 v1 = row[lane + 32];
            float v = ((v0.x + v0.y) + (v0.z + v0.w))
                    + ((v1.x + v1.y) + (v1.z + v1.w));
            // 3 xor rounds -> lane0 holds sum over lanes == 0 (mod 4)
            v += __shfl_xor_sync(0xffffffffu, v, 16);
            v += __shfl_xor_sync(0xffffffffu, v, 8);
            v += __shfl_xor_sync(0xffffffffu, v, 4);
            // parallel gather of the 3 remaining mod-4 classes
            float g1 = __shfl_sync(0xffffffffu, v, 1);
            float g2 = __shfl_sync(0xffffffffu, v, 2);
            float g3 = __shfl_sync(0xffffffffu, v, 3);
            if (lane == 0) {
                float s = (v + g1) + (g2 + g3);
                float o = tanha(s + myblin);
                float r;
                if (warp == 1 || warp == 3)
                    r = exp2f(0.5f * L2E * o);
                else if (warp >= 4)
                    r = exp2f(L2E * o);
                else
                    r = o;
                s_red[warp] = r;
            }
        }
        __syncthreads();   // bar2: s_red complete

        // redundant parallel tail: every thread computes the identical update
        // (same inputs, same IEEE ops -> bitwise identical). No 3rd barrier:
        // next iter's s_acc writes are fenced by bar2, s_red writes by bar1.
        const float4 rv0 = *(const float4*)&s_red[0];
        const float4 rv4 = *(const float4*)&s_red[4];
        const float2 ep = s_eps[i];
        float inv = __frcp_rn(rv4.x + rv4.y + rv4.z);
        lm0 = rv4.x * inv;
        lm1 = rv4.y * inv;
        lx = fmaf(rv0.y, ep.x, rv0.x);   // sigx*epx + o0
        ly = fmaf(rv0.w, ep.y, rv0.z);   // sigy*epy + o2
        // warp 7 (idle in stage 2) stores the output row
        if (warp == 7 && lane < 5) {
            float sm2 = rv4.z * inv;
            float v = (lane == 0) ? lx : (lane == 1) ? ly
                    : (lane == 2) ? lm0 : (lane == 3) ? lm1 : sm2;
            out[i * 5 + lane] = v;
        }
        // argmax(row[2:]) == 2  <=>  e6 strictly beats both (uniform predicate)
        if (rv4.z > rv4.x && rv4.z > rv4.y) break;  // remaining steps: no-ops
    }
}

extern "C" void kernel_launch(void* const* d_in, const int* in_sizes, int n_in,
                              void* d_out, int out_size) {
    const float* W_ih  = (const float*)d_in[0];
    // d_in[1] = W_hh: multiplied by a provably-zero hidden state -> unused.
    const float* b_ih  = (const float*)d_in[2];
    const float* b_hh  = (const float*)d_in[3];
    const float* W_lin = (const float*)d_in[4];
    const float* b_lin = (const float*)d_in[5];
    const int*   msp   = (const int*)d_in[6];
    float* out = (float*)d_out;

    sketch_decoder_kernel<<<1, NT>>>(W_ih, b_ih, b_hh, W_lin, b_lin, msp, out);
    (void)in_sizes; (void)n_in; (void)out_size;
}